// round 6
// baseline (speedup 1.0000x reference)
#include <cuda_runtime.h>
#include <math.h>
#include <stdint.h>

#define MAXN 100000
#define MAXE 1600000
#define NPAD (MAXN + 128)

// ---------------- scratch (static device arrays; no allocation) ----------------
__device__ float g_dinv[MAXN];            // deg accum, then rsqrt(deg)
__device__ int   g_cnt[MAXN];
__device__ int   g_cur[MAXN];
__device__ int   g_offs[MAXN + 1];
__device__ int2  g_edge[MAXE];            // {src, bitcast(norm)} CSR payload
__device__ float g_A2[(size_t)NPAD * 192]; // [XA(128) | h(64)] per node (fp32)
__device__ float g_c[192];
// W2 split into tf32 hi/lo, stored N-MAJOR: g_B*[j*192 + k]  (j=out col, k=inner)
__device__ float g_Bhi[192 * 192];
__device__ float g_Blo[192 * 192];

// ---------------- PTX helpers ----------------
__device__ __forceinline__ float tf32_rnd(float v) {
    uint32_t r;
    asm("cvt.rna.tf32.f32 %0, %1;" : "=r"(r) : "f"(v));
    return __uint_as_float(r);
}
__device__ __forceinline__ void mma_tf32(float* d, const uint32_t* a,
                                         uint32_t b0, uint32_t b1) {
    asm volatile(
        "mma.sync.aligned.m16n8k8.row.col.f32.tf32.tf32.f32 "
        "{%0,%1,%2,%3}, {%4,%5,%6,%7}, {%8,%9}, {%0,%1,%2,%3};"
        : "+f"(d[0]), "+f"(d[1]), "+f"(d[2]), "+f"(d[3])
        : "r"(a[0]), "r"(a[1]), "r"(a[2]), "r"(a[3]), "r"(b0), "r"(b1));
}
__device__ __forceinline__ uint32_t smem_u32(const void* p) {
    uint32_t a;
    asm("{ .reg .u64 t; cvta.to.shared.u64 t, %1; cvt.u32.u64 %0, t; }" : "=r"(a) : "l"(p));
    return a;
}
__device__ __forceinline__ void cpa16(uint32_t dst, const void* src) {
    asm volatile("cp.async.cg.shared.global [%0], [%1], 16;" :: "r"(dst), "l"(src));
}
__device__ __forceinline__ float sigf(float v) { return 1.f / (1.f + __expf(-v)); }

// ---------------- setup: init + W2 fold (tf32 hi/lo, n-major) + bias fold ----------------
__global__ void k_setup(const float* __restrict__ Wz, const float* __restrict__ Wr,
                        const float* __restrict__ Wh, const float* __restrict__ Lz,
                        const float* __restrict__ Lr, const float* __restrict__ Lh,
                        const float* __restrict__ bz, const float* __restrict__ br,
                        const float* __restrict__ bh, const float* __restrict__ bLz,
                        const float* __restrict__ bLr, const float* __restrict__ bLh,
                        int n) {
    int i = blockIdx.x * blockDim.x + threadIdx.x;
    if (i < n) { g_dinv[i] = 1.0f; g_cnt[i] = 0; g_cur[i] = 0; }
    if (i < 192 * 192) {
        int k = i / 192, j = i % 192;   // k: inner dim (A2 cols), j: output col
        float val;
        if (k < 128) {
            int g = j >> 6, jj = j & 63;
            const float* W = (g == 0) ? Wz : ((g == 1) ? Wr : Wh);
            const float* L = (g == 0) ? Lz : ((g == 1) ? Lr : Lh);
            float s = 0.f;
            #pragma unroll 8
            for (int m = 0; m < 64; m++) s = fmaf(W[k * 64 + m], L[m * 64 + jj], s);
            val = s;
        } else {
            int kk = k - 128;
            if (j < 64)       val = Lz[(64 + kk) * 64 + j];
            else if (j < 128) val = Lr[(64 + kk) * 64 + (j - 64)];
            else              val = 0.f;       // (h*R) @ Lh_bot handled in finalize
        }
        float hi = tf32_rnd(val);
        g_Bhi[j * 192 + k] = hi;                 // n-major
        g_Blo[j * 192 + k] = tf32_rnd(val - hi);
    }
    if (i < 192) {
        int g = i >> 6, jj = i & 63;
        const float* b  = (g == 0) ? bz  : ((g == 1) ? br  : bh);
        const float* L  = (g == 0) ? Lz  : ((g == 1) ? Lr  : Lh);
        const float* bL = (g == 0) ? bLz : ((g == 1) ? bLr : bLh);
        float s = bL[jj];
        #pragma unroll 8
        for (int m = 0; m < 64; m++) s = fmaf(b[m], L[m * 64 + jj], s);
        g_c[i] = s;
    }
}

// ---------------- degree histogram ----------------
__global__ void k_hist(const int* __restrict__ ei, const float* __restrict__ ew, int E) {
    int e = blockIdx.x * blockDim.x + threadIdx.x;
    if (e < E) {
        int c = ei[E + e];
        atomicAdd(&g_dinv[c], ew[e]);
        atomicAdd(&g_cnt[c], 1);
    }
}

// ---------------- dinv + exclusive scan, single block ----------------
__global__ void k_scan1(int n, int E) {
    int tid = threadIdx.x;
    for (int i = tid; i < n; i += 1024) g_dinv[i] = rsqrtf(g_dinv[i]);  // deg>=1 (self-loop)

    __shared__ int s[1024];
    int per = (n + 1023) >> 10;
    int start = tid * per;
    int end = start + per; if (end > n) end = n; if (start > n) start = n;
    int sum = 0;
    for (int i = start; i < end; i++) sum += g_cnt[i];
    s[tid] = sum; __syncthreads();
    int v = sum;
    for (int d = 1; d < 1024; d <<= 1) {
        int t = (tid >= d) ? s[tid - d] : 0;
        __syncthreads();
        s[tid] += t;
        __syncthreads();
    }
    int pre = s[tid] - v;
    for (int i = start; i < end; i++) { g_offs[i] = pre; pre += g_cnt[i]; }
    if (tid == 0) g_offs[n] = E;
}

// ---------------- CSR fill ----------------
__global__ void k_fill(const int* __restrict__ ei, const float* __restrict__ ew, int E) {
    int e = blockIdx.x * blockDim.x + threadIdx.x;
    if (e < E) {
        int r = ei[e];
        int c = ei[E + e];
        float nrm = g_dinv[r] * ew[e] * g_dinv[c];
        int pos = g_offs[c] + atomicAdd(&g_cur[c], 1);
        g_edge[pos] = make_int2(r, __float_as_int(nrm));
    }
}

// ---------------- aggregation + h copy: A2 = [XA | h] (fp32) ----------------
__global__ __launch_bounds__(256) void k_agg(const float* __restrict__ x,
                                             const float* __restrict__ h, int n) {
    int warp = threadIdx.x >> 5, lane = threadIdx.x & 31;
    int node = blockIdx.x * 8 + warp;
    if (node >= n) return;
    const float4* xv = (const float4*)x;
    float di = g_dinv[node];
    float s = di * di;
    float4 a = xv[(size_t)node * 32 + lane];
    float4 acc = make_float4(s * a.x, s * a.y, s * a.z, s * a.w);
    int j = g_offs[node], j1 = g_offs[node + 1];
    for (; j + 1 < j1; j += 2) {
        int2 e0 = g_edge[j], e1 = g_edge[j + 1];
        float4 v0 = xv[(size_t)e0.x * 32 + lane];
        float4 v1 = xv[(size_t)e1.x * 32 + lane];
        float w0 = __int_as_float(e0.y), w1 = __int_as_float(e1.y);
        acc.x = fmaf(w0, v0.x, acc.x); acc.y = fmaf(w0, v0.y, acc.y);
        acc.z = fmaf(w0, v0.z, acc.z); acc.w = fmaf(w0, v0.w, acc.w);
        acc.x = fmaf(w1, v1.x, acc.x); acc.y = fmaf(w1, v1.y, acc.y);
        acc.z = fmaf(w1, v1.z, acc.z); acc.w = fmaf(w1, v1.w, acc.w);
    }
    if (j < j1) {
        int2 e0 = g_edge[j];
        float4 v0 = xv[(size_t)e0.x * 32 + lane];
        float w0 = __int_as_float(e0.y);
        acc.x = fmaf(w0, v0.x, acc.x); acc.y = fmaf(w0, v0.y, acc.y);
        acc.z = fmaf(w0, v0.z, acc.z); acc.w = fmaf(w0, v0.w, acc.w);
    }
    ((float4*)g_A2)[(size_t)node * 48 + lane] = acc;
    if (lane < 16)
        ((float4*)g_A2)[(size_t)node * 48 + 32 + lane] =
            ((const float4*)h)[(size_t)node * 16 + lane];
}

// ---------------- fused GEMM + finalize ----------------
// CTA 128(M) x 192(N). K=192, 6 chunks of 32, double-buffered cp.async.
// A staged raw fp32 (split to tf32 hi/lo in regs). B staged n-major, pad 36:
// fragment reads conflict-free (bank = 4*gid + tig).
// 8 warps = 2(M) x 4(N); warp tile 64x48 = 4 m-frags x 6 n-frags (m16n8k8).
// Epilogue: accs -> smem Pbuf, then gates/tanh/GRU/head in-kernel.
#define PAD36 36
#define F_A   0
#define F_BH  4608
#define F_BL  11520
#define F_BUF 18432
#define SMEM_GEMM_BYTES (2 * F_BUF * 4)
#define PP 200

__global__ __launch_bounds__(256) void k_gemm_fused(
        const float* __restrict__ h, const float* __restrict__ Lh,
        const float* __restrict__ Wo, const float* __restrict__ bo,
        float* __restrict__ out, int n) {
    extern __shared__ float smf[];
    uint32_t sb = smem_u32(smf);
    int tid = threadIdx.x;
    int wid = tid >> 5, lane = tid & 31;
    int warpM = wid >> 2, warpN = wid & 3;
    int gid = lane >> 2, tig = lane & 3;
    int rowBase = blockIdx.x * 128;

    float d[4][6][4];
    #pragma unroll
    for (int mf = 0; mf < 4; mf++)
        #pragma unroll
        for (int nt = 0; nt < 6; nt++)
            #pragma unroll
            for (int q = 0; q < 4; q++) d[mf][nt][q] = 0.f;

    // --- stage chunk 0 ---
    {
        uint32_t base = sb;
        const float* Ag = g_A2 + (size_t)rowBase * 192;
        #pragma unroll
        for (int t = 0; t < 4; t++) {
            int idx = tid + t * 256;
            int row = idx >> 3, q = idx & 7;
            cpa16(base + (F_A + row * PAD36 + q * 4) * 4, Ag + (size_t)row * 192 + q * 4);
        }
        #pragma unroll
        for (int t = 0; t < 6; t++) {
            int idx = tid + t * 256;
            int j = idx >> 3, q = idx & 7;
            cpa16(base + (F_BH + j * PAD36 + q * 4) * 4, g_Bhi + j * 192 + q * 4);
            cpa16(base + (F_BL + j * PAD36 + q * 4) * 4, g_Blo + j * 192 + q * 4);
        }
        asm volatile("cp.async.commit_group;");
    }

    for (int c = 0; c < 6; c++) {
        if (c + 1 < 6) {
            uint32_t base = sb + ((c + 1) & 1) * (F_BUF * 4);
            int cc = c + 1;
            const float* Ag = g_A2 + (size_t)rowBase * 192 + cc * 32;
            #pragma unroll
            for (int t = 0; t < 4; t++) {
                int idx = tid + t * 256;
                int row = idx >> 3, q = idx & 7;
                cpa16(base + (F_A + row * PAD36 + q * 4) * 4, Ag + (size_t)row * 192 + q * 4);
            }
            const float* Bh = g_Bhi + cc * 32;
            const float* Bl = g_Blo + cc * 32;
            #pragma unroll
            for (int t = 0; t < 6; t++) {
                int idx = tid + t * 256;
                int j = idx >> 3, q = idx & 7;
                cpa16(base + (F_BH + j * PAD36 + q * 4) * 4, Bh + j * 192 + q * 4);
                cpa16(base + (F_BL + j * PAD36 + q * 4) * 4, Bl + j * 192 + q * 4);
            }
            asm volatile("cp.async.commit_group;");
            asm volatile("cp.async.wait_group 1;");
        } else {
            asm volatile("cp.async.wait_group 0;");
        }
        __syncthreads();

        const float*    As  = smf + (c & 1) * F_BUF + F_A;
        const uint32_t* sBh = (const uint32_t*)(smf + (c & 1) * F_BUF + F_BH);
        const uint32_t* sBl = (const uint32_t*)(smf + (c & 1) * F_BUF + F_BL);

        #pragma unroll
        for (int ks = 0; ks < 4; ks++) {
            uint32_t ahi[4][4], alo[4][4];
            #pragma unroll
            for (int mf = 0; mf < 4; mf++) {
                int r0 = (warpM * 64 + mf * 16 + gid) * PAD36 + ks * 8 + tig;
                float a0 = As[r0],            a1 = As[r0 + 8 * PAD36];
                float a2 = As[r0 + 4],        a3 = As[r0 + 4 + 8 * PAD36];
                float h0 = tf32_rnd(a0), h1 = tf32_rnd(a1);
                float h2 = tf32_rnd(a2), h3 = tf32_rnd(a3);
                ahi[mf][0] = __float_as_uint(h0); ahi[mf][1] = __float_as_uint(h1);
                ahi[mf][2] = __float_as_uint(h2); ahi[mf][3] = __float_as_uint(h3);
                alo[mf][0] = __float_as_uint(tf32_rnd(a0 - h0));
                alo[mf][1] = __float_as_uint(tf32_rnd(a1 - h1));
                alo[mf][2] = __float_as_uint(tf32_rnd(a2 - h2));
                alo[mf][3] = __float_as_uint(tf32_rnd(a3 - h3));
            }
            #pragma unroll
            for (int nt = 0; nt < 6; nt++) {
                int nn = warpN * 48 + nt * 8 + gid;
                int kb = nn * PAD36 + ks * 8 + tig;      // bank = 4*gid + tig: conflict-free
                uint32_t bh0 = sBh[kb], bh1 = sBh[kb + 4];
                uint32_t bl0 = sBl[kb], bl1 = sBl[kb + 4];
                #pragma unroll
                for (int mf = 0; mf < 4; mf++) {
                    mma_tf32(d[mf][nt], ahi[mf], bh0, bh1);
                    mma_tf32(d[mf][nt], ahi[mf], bl0, bl1);
                    mma_tf32(d[mf][nt], alo[mf], bh0, bh1);
                }
            }
        }
        __syncthreads();
    }

    // ---- epilogue: accumulators -> Pbuf (reuse staging smem) ----
    float* Pbuf = smf;                         // 128 x PP floats = 25600
    float* Lhb  = smf + 25600;                 // 64 x 65 = 4160
    float* sWo  = smf + 29760;                 // 64
    float* sc   = smf + 29824;                 // 192
    #pragma unroll
    for (int mf = 0; mf < 4; mf++) {
        int rl = warpM * 64 + mf * 16 + gid;
        #pragma unroll
        for (int nt = 0; nt < 6; nt++) {
            int col = warpN * 48 + nt * 8 + tig * 2;
            *(float2*)(Pbuf + rl * PP + col)       = make_float2(d[mf][nt][0], d[mf][nt][1]);
            *(float2*)(Pbuf + (rl + 8) * PP + col) = make_float2(d[mf][nt][2], d[mf][nt][3]);
        }
    }
    // load finalize weights
    for (int i = tid; i < 4096; i += 256) {
        int k = i >> 6, j = i & 63;
        Lhb[k * 65 + j] = Lh[(64 + k) * 64 + j];
    }
    if (tid < 64) sWo[tid] = Wo[tid];
    if (tid < 192) sc[tid] = g_c[tid];
    __syncthreads();

    // ---- finalize: each warp handles 16 nodes ----
    float bo0 = bo[0];
    #pragma unroll 1
    for (int i = 0; i < 16; i++) {
        int nl = wid * 16 + i;
        int node = rowBase + nl;
        if (node >= n) break;
        const float* p = Pbuf + nl * PP;
        float z0 = sigf(p[lane]       + sc[lane]);
        float z1 = sigf(p[lane + 32]  + sc[lane + 32]);
        float r0 = sigf(p[lane + 64]  + sc[lane + 64]);
        float r1 = sigf(p[lane + 96]  + sc[lane + 96]);
        float q0 =      p[lane + 128] + sc[lane + 128];
        float q1 =      p[lane + 160] + sc[lane + 160];

        float h0 = h[(size_t)node * 64 + lane];
        float h1 = h[(size_t)node * 64 + lane + 32];
        float v0 = h0 * r0, v1 = h1 * r1;

        float acc0 = q0, acc1 = q1;
        #pragma unroll
        for (int k = 0; k < 32; k++) {
            float vk = __shfl_sync(0xffffffffu, v0, k);
            acc0 = fmaf(vk, Lhb[k * 65 + lane], acc0);
            acc1 = fmaf(vk, Lhb[k * 65 + lane + 32], acc1);
        }
        #pragma unroll
        for (int k = 0; k < 32; k++) {
            float vk = __shfl_sync(0xffffffffu, v1, k);
            acc0 = fmaf(vk, Lhb[(k + 32) * 65 + lane], acc0);
            acc1 = fmaf(vk, Lhb[(k + 32) * 65 + lane + 32], acc1);
        }
        float t0 = tanhf(acc0), t1 = tanhf(acc1);
        float hn0 = z0 * h0 + (1.f - z0) * t0;
        float hn1 = z1 * h1 + (1.f - z1) * t1;

        out[n + (size_t)node * 64 + lane]      = hn0;
        out[n + (size_t)node * 64 + lane + 32] = hn1;

        float dot = hn0 * sWo[lane] + hn1 * sWo[lane + 32];
        #pragma unroll
        for (int o = 16; o; o >>= 1) dot += __shfl_down_sync(0xffffffffu, dot, o);
        if (lane == 0) out[node] = dot + bo0;
    }
}

// ---------------- launcher ----------------
extern "C" void kernel_launch(void* const* d_in, const int* in_sizes, int n_in,
                              void* d_out, int out_size) {
    const float* x   = (const float*)d_in[0];
    const int*   ei  = (const int*)  d_in[1];
    const float* ew  = (const float*)d_in[2];
    const float* h   = (const float*)d_in[3];
    const float* Wz  = (const float*)d_in[4];
    const float* bz  = (const float*)d_in[5];
    const float* Wr  = (const float*)d_in[6];
    const float* br  = (const float*)d_in[7];
    const float* Wh  = (const float*)d_in[8];
    const float* bh  = (const float*)d_in[9];
    const float* Lz  = (const float*)d_in[10];
    const float* bLz = (const float*)d_in[11];
    const float* Lr  = (const float*)d_in[12];
    const float* bLr = (const float*)d_in[13];
    const float* Lh  = (const float*)d_in[14];
    const float* bLh = (const float*)d_in[15];
    const float* Wo  = (const float*)d_in[16];
    const float* bo  = (const float*)d_in[17];
    float* out = (float*)d_out;

    int N = in_sizes[0] / 128;
    int E = in_sizes[2];
    int setup_elems = (N > 192 * 192) ? N : 192 * 192;

    cudaFuncSetAttribute(k_gemm_fused, cudaFuncAttributeMaxDynamicSharedMemorySize,
                         SMEM_GEMM_BYTES);

    k_setup<<<(setup_elems + 255) / 256, 256>>>(Wz, Wr, Wh, Lz, Lr, Lh,
                                                bz, br, bh, bLz, bLr, bLh, N);
    k_hist<<<(E + 255) / 256, 256>>>(ei, ew, E);
    k_scan1<<<1, 1024>>>(N, E);
    k_fill<<<(E + 255) / 256, 256>>>(ei, ew, E);
    k_agg<<<(N + 7) / 8, 256>>>(x, h, N);
    k_gemm_fused<<<(N + 127) / 128, 256, SMEM_GEMM_BYTES>>>(h, Lh, Wo, bo, out, N);
}

// round 7
// speedup vs baseline: 1.1257x; 1.1257x over previous
#include <cuda_runtime.h>
#include <cuda_bf16.h>
#include <math.h>
#include <stdint.h>

#define MAXN 100000
#define MAXE 1600000
#define NPAD (MAXN + 128)

// ---------------- scratch (static device arrays; no allocation) ----------------
__device__ float g_dinv[MAXN];            // deg accum, then rsqrt(deg)
__device__ int   g_cnt[MAXN];
__device__ int   g_cur[MAXN];
__device__ int   g_offs[MAXN + 1];
__device__ int2  g_edge[MAXE];            // {src, bitcast(norm)} CSR payload
// A = [XA(128) | h(64)] per node, pre-split bf16 hi/lo, packed bf16x2 along k:
// g_Ahp[node*96 + kp] holds {k=2kp (lo16), k=2kp+1 (hi16)}
__device__ uint32_t g_Ahp[(size_t)NPAD * 96];
__device__ uint32_t g_Alp[(size_t)NPAD * 96];
__device__ float g_c[192];
// W2 split bf16 hi/lo, n-major: g_B*16[j*192 + k]
__device__ unsigned short g_Bh16[192 * 192];
__device__ unsigned short g_Bl16[192 * 192];

// ---------------- helpers ----------------
__device__ __forceinline__ void mma_bf16(float* d, const uint32_t* a,
                                         uint32_t b0, uint32_t b1) {
    asm volatile(
        "mma.sync.aligned.m16n8k16.row.col.f32.bf16.bf16.f32 "
        "{%0,%1,%2,%3}, {%4,%5,%6,%7}, {%8,%9}, {%0,%1,%2,%3};"
        : "+f"(d[0]), "+f"(d[1]), "+f"(d[2]), "+f"(d[3])
        : "r"(a[0]), "r"(a[1]), "r"(a[2]), "r"(a[3]), "r"(b0), "r"(b1));
}
__device__ __forceinline__ uint32_t smem_u32(const void* p) {
    uint32_t a;
    asm("{ .reg .u64 t; cvta.to.shared.u64 t, %1; cvt.u32.u64 %0, t; }" : "=r"(a) : "l"(p));
    return a;
}
__device__ __forceinline__ void cpa16(uint32_t dst, const void* src) {
    asm volatile("cp.async.cg.shared.global [%0], [%1], 16;" :: "r"(dst), "l"(src));
}
__device__ __forceinline__ float sigf(float v) { return 1.f / (1.f + __expf(-v)); }
// pack two fp32 into bf16x2 hi parts + bf16x2 lo remainders
__device__ __forceinline__ void split2(float f0, float f1, uint32_t& hi, uint32_t& lo) {
    __nv_bfloat162 p = __floats2bfloat162_rn(f0, f1);   // .x=f0 -> lower 16 bits
    float h0 = __low2float(p), h1 = __high2float(p);
    __nv_bfloat162 q = __floats2bfloat162_rn(f0 - h0, f1 - h1);
    hi = *reinterpret_cast<uint32_t*>(&p);
    lo = *reinterpret_cast<uint32_t*>(&q);
}

// ---------------- setup: init + W2 fold (bf16 hi/lo, n-major) + bias fold ----------------
__global__ void k_setup(const float* __restrict__ Wz, const float* __restrict__ Wr,
                        const float* __restrict__ Wh, const float* __restrict__ Lz,
                        const float* __restrict__ Lr, const float* __restrict__ Lh,
                        const float* __restrict__ bz, const float* __restrict__ br,
                        const float* __restrict__ bh, const float* __restrict__ bLz,
                        const float* __restrict__ bLr, const float* __restrict__ bLh,
                        int n) {
    int i = blockIdx.x * blockDim.x + threadIdx.x;
    if (i < n) { g_dinv[i] = 1.0f; g_cnt[i] = 0; g_cur[i] = 0; }
    if (i < 192 * 192) {
        int k = i / 192, j = i % 192;   // k: inner dim (A cols), j: output col
        float val;
        if (k < 128) {
            int g = j >> 6, jj = j & 63;
            const float* W = (g == 0) ? Wz : ((g == 1) ? Wr : Wh);
            const float* L = (g == 0) ? Lz : ((g == 1) ? Lr : Lh);
            float s = 0.f;
            #pragma unroll 8
            for (int m = 0; m < 64; m++) s = fmaf(W[k * 64 + m], L[m * 64 + jj], s);
            val = s;
        } else {
            int kk = k - 128;
            if (j < 64)       val = Lz[(64 + kk) * 64 + j];
            else if (j < 128) val = Lr[(64 + kk) * 64 + (j - 64)];
            else              val = 0.f;       // (h*R) @ Lh_bot handled in finalize
        }
        __nv_bfloat16 hb = __float2bfloat16(val);
        float hf = __bfloat162float(hb);
        __nv_bfloat16 lb = __float2bfloat16(val - hf);
        g_Bh16[j * 192 + k] = *reinterpret_cast<unsigned short*>(&hb);
        g_Bl16[j * 192 + k] = *reinterpret_cast<unsigned short*>(&lb);
    }
    if (i < 192) {
        int g = i >> 6, jj = i & 63;
        const float* b  = (g == 0) ? bz  : ((g == 1) ? br  : bh);
        const float* L  = (g == 0) ? Lz  : ((g == 1) ? Lr  : Lh);
        const float* bL = (g == 0) ? bLz : ((g == 1) ? bLr : bLh);
        float s = bL[jj];
        #pragma unroll 8
        for (int m = 0; m < 64; m++) s = fmaf(b[m], L[m * 64 + jj], s);
        g_c[i] = s;
    }
}

// ---------------- degree histogram ----------------
__global__ void k_hist(const int* __restrict__ ei, const float* __restrict__ ew, int E) {
    int e = blockIdx.x * blockDim.x + threadIdx.x;
    if (e < E) {
        int c = ei[E + e];
        atomicAdd(&g_dinv[c], ew[e]);
        atomicAdd(&g_cnt[c], 1);
    }
}

// ---------------- dinv + exclusive scan, single block ----------------
__global__ void k_scan1(int n, int E) {
    int tid = threadIdx.x;
    for (int i = tid; i < n; i += 1024) g_dinv[i] = rsqrtf(g_dinv[i]);  // deg>=1 (self-loop)

    __shared__ int s[1024];
    int per = (n + 1023) >> 10;
    int start = tid * per;
    int end = start + per; if (end > n) end = n; if (start > n) start = n;
    int sum = 0;
    for (int i = start; i < end; i++) sum += g_cnt[i];
    s[tid] = sum; __syncthreads();
    int v = sum;
    for (int d = 1; d < 1024; d <<= 1) {
        int t = (tid >= d) ? s[tid - d] : 0;
        __syncthreads();
        s[tid] += t;
        __syncthreads();
    }
    int pre = s[tid] - v;
    for (int i = start; i < end; i++) { g_offs[i] = pre; pre += g_cnt[i]; }
    if (tid == 0) g_offs[n] = E;
}

// ---------------- CSR fill ----------------
__global__ void k_fill(const int* __restrict__ ei, const float* __restrict__ ew, int E) {
    int e = blockIdx.x * blockDim.x + threadIdx.x;
    if (e < E) {
        int r = ei[e];
        int c = ei[E + e];
        float nrm = g_dinv[r] * ew[e] * g_dinv[c];
        int pos = g_offs[c] + atomicAdd(&g_cur[c], 1);
        g_edge[pos] = make_int2(r, __float_as_int(nrm));
    }
}

// ---------------- aggregation + h copy + bf16 hi/lo split ----------------
__global__ __launch_bounds__(256) void k_agg(const float* __restrict__ x,
                                             const float* __restrict__ h, int n) {
    int warp = threadIdx.x >> 5, lane = threadIdx.x & 31;
    int node = blockIdx.x * 8 + warp;
    if (node >= n) return;
    const float4* xv = (const float4*)x;
    float di = g_dinv[node];
    float s = di * di;
    float4 a = xv[(size_t)node * 32 + lane];
    float4 acc = make_float4(s * a.x, s * a.y, s * a.z, s * a.w);
    int j = g_offs[node], j1 = g_offs[node + 1];
    for (; j + 1 < j1; j += 2) {
        int2 e0 = g_edge[j], e1 = g_edge[j + 1];
        float4 v0 = xv[(size_t)e0.x * 32 + lane];
        float4 v1 = xv[(size_t)e1.x * 32 + lane];
        float w0 = __int_as_float(e0.y), w1 = __int_as_float(e1.y);
        acc.x = fmaf(w0, v0.x, acc.x); acc.y = fmaf(w0, v0.y, acc.y);
        acc.z = fmaf(w0, v0.z, acc.z); acc.w = fmaf(w0, v0.w, acc.w);
        acc.x = fmaf(w1, v1.x, acc.x); acc.y = fmaf(w1, v1.y, acc.y);
        acc.z = fmaf(w1, v1.z, acc.z); acc.w = fmaf(w1, v1.w, acc.w);
    }
    if (j < j1) {
        int2 e0 = g_edge[j];
        float4 v0 = xv[(size_t)e0.x * 32 + lane];
        float w0 = __int_as_float(e0.y);
        acc.x = fmaf(w0, v0.x, acc.x); acc.y = fmaf(w0, v0.y, acc.y);
        acc.z = fmaf(w0, v0.z, acc.z); acc.w = fmaf(w0, v0.w, acc.w);
    }
    // pack k = 4*lane .. 4*lane+3 -> kp = 2*lane, 2*lane+1
    uint32_t h0, l0, h1, l1;
    split2(acc.x, acc.y, h0, l0);
    split2(acc.z, acc.w, h1, l1);
    *(uint2*)&g_Ahp[(size_t)node * 96 + lane * 2] = make_uint2(h0, h1);
    *(uint2*)&g_Alp[(size_t)node * 96 + lane * 2] = make_uint2(l0, l1);
    if (lane < 16) {
        float4 hv = ((const float4*)h)[(size_t)node * 16 + lane];
        split2(hv.x, hv.y, h0, l0);
        split2(hv.z, hv.w, h1, l1);
        *(uint2*)&g_Ahp[(size_t)node * 96 + 64 + lane * 2] = make_uint2(h0, h1);
        *(uint2*)&g_Alp[(size_t)node * 96 + 64 + lane * 2] = make_uint2(l0, l1);
    }
}

// ---------------- fused 3xBF16 GEMM + finalize ----------------
// CTA 128(M) x 192(N). K=192 in 6 chunks of 32 (16 bf16x2 pairs), double-buffered.
// Pads of 20 u32/row -> all fragment LDS conflict-free.
// 8 warps = 2(M) x 4(N); warp tile 64x48 = 4 m-frags x 6 n-frags (m16n8k16).
#define PADK 20
#define F_A   0
#define F_AL  2560
#define F_BH  5120
#define F_BL  8960
#define F_BUF 12800
#define PP 200
#define SMEM_GEMM_BYTES 120064

__global__ __launch_bounds__(256) void k_gemm_fused(
        const float* __restrict__ h, const float* __restrict__ Lh,
        const float* __restrict__ Wo, const float* __restrict__ bo,
        float* __restrict__ out, int n) {
    extern __shared__ float smf[];
    uint32_t sb = smem_u32(smf);
    int tid = threadIdx.x;
    int wid = tid >> 5, lane = tid & 31;
    int warpM = wid >> 2, warpN = wid & 3;
    int gid = lane >> 2, tig = lane & 3;
    int rowBase = blockIdx.x * 128;

    float d[4][6][4];
    #pragma unroll
    for (int mf = 0; mf < 4; mf++)
        #pragma unroll
        for (int nt = 0; nt < 6; nt++)
            #pragma unroll
            for (int q = 0; q < 4; q++) d[mf][nt][q] = 0.f;

    // --- stage chunk 0 ---
    {
        uint32_t base = sb;
        const uint32_t* Ah = g_Ahp + (size_t)rowBase * 96;
        const uint32_t* Al = g_Alp + (size_t)rowBase * 96;
        #pragma unroll
        for (int t = 0; t < 2; t++) {                 // 128 rows x 4 xfers = 512 per matrix
            int idx = tid + t * 256;
            int row = idx >> 2, q = idx & 3;
            cpa16(base + (F_A  + row * PADK + q * 4) * 4, Ah + (size_t)row * 96 + q * 4);
            cpa16(base + (F_AL + row * PADK + q * 4) * 4, Al + (size_t)row * 96 + q * 4);
        }
        #pragma unroll
        for (int t = 0; t < 3; t++) {                 // 192 rows x 4 xfers = 768 per matrix
            int idx = tid + t * 256;
            int jrow = idx >> 2, q = idx & 3;
            cpa16(base + (F_BH + jrow * PADK + q * 4) * 4, g_Bh16 + jrow * 192 + q * 8);
            cpa16(base + (F_BL + jrow * PADK + q * 4) * 4, g_Bl16 + jrow * 192 + q * 8);
        }
        asm volatile("cp.async.commit_group;");
    }

    for (int c = 0; c < 6; c++) {
        if (c + 1 < 6) {
            uint32_t base = sb + ((c + 1) & 1) * (F_BUF * 4);
            int cc = c + 1;
            const uint32_t* Ah = g_Ahp + (size_t)rowBase * 96 + cc * 16;
            const uint32_t* Al = g_Alp + (size_t)rowBase * 96 + cc * 16;
            #pragma unroll
            for (int t = 0; t < 2; t++) {
                int idx = tid + t * 256;
                int row = idx >> 2, q = idx & 3;
                cpa16(base + (F_A  + row * PADK + q * 4) * 4, Ah + (size_t)row * 96 + q * 4);
                cpa16(base + (F_AL + row * PADK + q * 4) * 4, Al + (size_t)row * 96 + q * 4);
            }
            const unsigned short* Bh = g_Bh16 + cc * 32;
            const unsigned short* Bl = g_Bl16 + cc * 32;
            #pragma unroll
            for (int t = 0; t < 3; t++) {
                int idx = tid + t * 256;
                int jrow = idx >> 2, q = idx & 3;
                cpa16(base + (F_BH + jrow * PADK + q * 4) * 4, Bh + jrow * 192 + q * 8);
                cpa16(base + (F_BL + jrow * PADK + q * 4) * 4, Bl + jrow * 192 + q * 8);
            }
            asm volatile("cp.async.commit_group;");
            asm volatile("cp.async.wait_group 1;");
        } else {
            asm volatile("cp.async.wait_group 0;");
        }
        __syncthreads();

        const uint32_t* Ah = (const uint32_t*)smf + (c & 1) * F_BUF + F_A;
        const uint32_t* Al = (const uint32_t*)smf + (c & 1) * F_BUF + F_AL;
        const uint32_t* Bh = (const uint32_t*)smf + (c & 1) * F_BUF + F_BH;
        const uint32_t* Bl = (const uint32_t*)smf + (c & 1) * F_BUF + F_BL;

        #pragma unroll
        for (int ks = 0; ks < 2; ks++) {
            uint32_t ahi[4][4], alo[4][4];
            #pragma unroll
            for (int mf = 0; mf < 4; mf++) {
                int r0 = (warpM * 64 + mf * 16 + gid) * PADK + ks * 8 + tig;
                int r1 = r0 + 8 * PADK;
                ahi[mf][0] = Ah[r0];     ahi[mf][1] = Ah[r1];
                ahi[mf][2] = Ah[r0 + 4]; ahi[mf][3] = Ah[r1 + 4];
                alo[mf][0] = Al[r0];     alo[mf][1] = Al[r1];
                alo[mf][2] = Al[r0 + 4]; alo[mf][3] = Al[r1 + 4];
            }
            #pragma unroll
            for (int nt = 0; nt < 6; nt++) {
                int nn = warpN * 48 + nt * 8 + gid;
                int kb = nn * PADK + ks * 8 + tig;     // bank (20*gid+tig)%32: conflict-free
                uint32_t bh0 = Bh[kb], bh1 = Bh[kb + 4];
                uint32_t bl0 = Bl[kb], bl1 = Bl[kb + 4];
                #pragma unroll
                for (int mf = 0; mf < 4; mf++) {
                    mma_bf16(d[mf][nt], ahi[mf], bh0, bh1);
                    mma_bf16(d[mf][nt], ahi[mf], bl0, bl1);
                    mma_bf16(d[mf][nt], alo[mf], bh0, bh1);
                }
            }
        }
        __syncthreads();
    }

    // ---- epilogue: accumulators -> Pbuf (reuse staging smem) ----
    float* Pbuf = smf;                         // 128 x PP = 25600 floats
    float* Lhb  = smf + 25600;                 // 64 x 65 = 4160
    float* sWo  = smf + 29760;                 // 64
    float* sc   = smf + 29824;                 // 192
    #pragma unroll
    for (int mf = 0; mf < 4; mf++) {
        int rl = warpM * 64 + mf * 16 + gid;
        #pragma unroll
        for (int nt = 0; nt < 6; nt++) {
            int col = warpN * 48 + nt * 8 + tig * 2;
            *(float2*)(Pbuf + rl * PP + col)       = make_float2(d[mf][nt][0], d[mf][nt][1]);
            *(float2*)(Pbuf + (rl + 8) * PP + col) = make_float2(d[mf][nt][2], d[mf][nt][3]);
        }
    }
    for (int i = tid; i < 4096; i += 256) {
        int k = i >> 6, j = i & 63;
        Lhb[k * 65 + j] = Lh[(64 + k) * 64 + j];
    }
    if (tid < 64) sWo[tid] = Wo[tid];
    if (tid < 192) sc[tid] = g_c[tid];
    __syncthreads();

    // ---- finalize: each warp handles 16 nodes ----
    float bo0 = bo[0];
    #pragma unroll 1
    for (int i = 0; i < 16; i++) {
        int nl = wid * 16 + i;
        int node = rowBase + nl;
        if (node >= n) break;
        const float* p = Pbuf + nl * PP;
        float z0 = sigf(p[lane]       + sc[lane]);
        float z1 = sigf(p[lane + 32]  + sc[lane + 32]);
        float r0 = sigf(p[lane + 64]  + sc[lane + 64]);
        float r1 = sigf(p[lane + 96]  + sc[lane + 96]);
        float q0 =      p[lane + 128] + sc[lane + 128];
        float q1 =      p[lane + 160] + sc[lane + 160];

        float h0 = h[(size_t)node * 64 + lane];
        float h1 = h[(size_t)node * 64 + lane + 32];
        float v0 = h0 * r0, v1 = h1 * r1;

        float acc0 = q0, acc1 = q1;
        #pragma unroll
        for (int k = 0; k < 32; k++) {
            float vk = __shfl_sync(0xffffffffu, v0, k);
            acc0 = fmaf(vk, Lhb[k * 65 + lane], acc0);
            acc1 = fmaf(vk, Lhb[k * 65 + lane + 32], acc1);
        }
        #pragma unroll
        for (int k = 0; k < 32; k++) {
            float vk = __shfl_sync(0xffffffffu, v1, k);
            acc0 = fmaf(vk, Lhb[(k + 32) * 65 + lane], acc0);
            acc1 = fmaf(vk, Lhb[(k + 32) * 65 + lane + 32], acc1);
        }
        float t0 = tanhf(acc0), t1 = tanhf(acc1);
        float hn0 = z0 * h0 + (1.f - z0) * t0;
        float hn1 = z1 * h1 + (1.f - z1) * t1;

        out[n + (size_t)node * 64 + lane]      = hn0;
        out[n + (size_t)node * 64 + lane + 32] = hn1;

        float dot = hn0 * sWo[lane] + hn1 * sWo[lane + 32];
        #pragma unroll
        for (int o = 16; o; o >>= 1) dot += __shfl_down_sync(0xffffffffu, dot, o);
        if (lane == 0) out[node] = dot + bo0;
    }
}

// ---------------- launcher ----------------
extern "C" void kernel_launch(void* const* d_in, const int* in_sizes, int n_in,
                              void* d_out, int out_size) {
    const float* x   = (const float*)d_in[0];
    const int*   ei  = (const int*)  d_in[1];
    const float* ew  = (const float*)d_in[2];
    const float* h   = (const float*)d_in[3];
    const float* Wz  = (const float*)d_in[4];
    const float* bz  = (const float*)d_in[5];
    const float* Wr  = (const float*)d_in[6];
    const float* br  = (const float*)d_in[7];
    const float* Wh  = (const float*)d_in[8];
    const float* bh  = (const float*)d_in[9];
    const float* Lz  = (const float*)d_in[10];
    const float* bLz = (const float*)d_in[11];
    const float* Lr  = (const float*)d_in[12];
    const float* bLr = (const float*)d_in[13];
    const float* Lh  = (const float*)d_in[14];
    const float* bLh = (const float*)d_in[15];
    const float* Wo  = (const float*)d_in[16];
    const float* bo  = (const float*)d_in[17];
    float* out = (float*)d_out;

    int N = in_sizes[0] / 128;
    int E = in_sizes[2];
    int setup_elems = (N > 192 * 192) ? N : 192 * 192;

    cudaFuncSetAttribute(k_gemm_fused, cudaFuncAttributeMaxDynamicSharedMemorySize,
                         SMEM_GEMM_BYTES);

    k_setup<<<(setup_elems + 255) / 256, 256>>>(Wz, Wr, Wh, Lz, Lr, Lh,
                                                bz, br, bh, bLz, bLr, bLh, N);
    k_hist<<<(E + 255) / 256, 256>>>(ei, ew, E);
    k_scan1<<<1, 1024>>>(N, E);
    k_fill<<<(E + 255) / 256, 256>>>(ei, ew, E);
    k_agg<<<(N + 7) / 8, 256>>>(x, h, N);
    k_gemm_fused<<<(N + 127) / 128, 256, SMEM_GEMM_BYTES>>>(h, Lh, Wo, bo, out, N);
}

// round 8
// speedup vs baseline: 1.2737x; 1.1314x over previous
#include <cuda_runtime.h>
#include <cuda_bf16.h>
#include <math.h>
#include <stdint.h>

#define MAXN 100000
#define MAXE 1600000
#define NPAD (MAXN + 128)

// ---------------- scratch ----------------
__device__ float g_dinv[MAXN];
__device__ int   g_cnt[MAXN];
__device__ int   g_offs[MAXN + 1];
__device__ int   g_rank[MAXE];
__device__ int2  g_edge[MAXE];            // {src, bitcast(norm)}
// A = [XA(128) | h(64)] bf16 hi/lo, packed bf16x2 along k: [node][kp<96]
__device__ uint32_t g_Ahp[(size_t)NPAD * 96];
__device__ uint32_t g_Alp[(size_t)NPAD * 96];
__device__ float g_c[192];
// W2 bf16 hi/lo, n-major [j][k]
__device__ unsigned short g_Bh16[192 * 192];
__device__ unsigned short g_Bl16[192 * 192];

// ---------------- helpers ----------------
__device__ __forceinline__ void mma_bf16(float* d, const uint32_t* a,
                                         uint32_t b0, uint32_t b1) {
    asm volatile(
        "mma.sync.aligned.m16n8k16.row.col.f32.bf16.bf16.f32 "
        "{%0,%1,%2,%3}, {%4,%5,%6,%7}, {%8,%9}, {%0,%1,%2,%3};"
        : "+f"(d[0]), "+f"(d[1]), "+f"(d[2]), "+f"(d[3])
        : "r"(a[0]), "r"(a[1]), "r"(a[2]), "r"(a[3]), "r"(b0), "r"(b1));
}
__device__ __forceinline__ void ldsm4(uint32_t& r0, uint32_t& r1, uint32_t& r2,
                                      uint32_t& r3, uint32_t addr) {
    asm volatile("ldmatrix.sync.aligned.m8n8.x4.shared.b16 {%0,%1,%2,%3}, [%4];"
                 : "=r"(r0), "=r"(r1), "=r"(r2), "=r"(r3) : "r"(addr));
}
__device__ __forceinline__ uint32_t smem_u32(const void* p) {
    uint32_t a;
    asm("{ .reg .u64 t; cvta.to.shared.u64 t, %1; cvt.u32.u64 %0, t; }" : "=r"(a) : "l"(p));
    return a;
}
__device__ __forceinline__ void cpa16(uint32_t dst, const void* src) {
    asm volatile("cp.async.cg.shared.global [%0], [%1], 16;" :: "r"(dst), "l"(src));
}
__device__ __forceinline__ float sigf(float v) { return 1.f / (1.f + __expf(-v)); }
__device__ __forceinline__ void split2(float f0, float f1, uint32_t& hi, uint32_t& lo) {
    __nv_bfloat162 p = __floats2bfloat162_rn(f0, f1);
    float h0 = __low2float(p), h1 = __high2float(p);
    __nv_bfloat162 q = __floats2bfloat162_rn(f0 - h0, f1 - h1);
    hi = *reinterpret_cast<uint32_t*>(&p);
    lo = *reinterpret_cast<uint32_t*>(&q);
}

// ---------------- setup ----------------
__global__ void k_setup(const float* __restrict__ Wz, const float* __restrict__ Wr,
                        const float* __restrict__ Wh, const float* __restrict__ Lz,
                        const float* __restrict__ Lr, const float* __restrict__ Lh,
                        const float* __restrict__ bz, const float* __restrict__ br,
                        const float* __restrict__ bh, const float* __restrict__ bLz,
                        const float* __restrict__ bLr, const float* __restrict__ bLh,
                        int n) {
    int i = blockIdx.x * blockDim.x + threadIdx.x;
    if (i < n) { g_dinv[i] = 1.0f; g_cnt[i] = 0; }
    if (i < 192 * 192) {
        int k = i / 192, j = i % 192;
        float val;
        if (k < 128) {
            int g = j >> 6, jj = j & 63;
            const float* W = (g == 0) ? Wz : ((g == 1) ? Wr : Wh);
            const float* L = (g == 0) ? Lz : ((g == 1) ? Lr : Lh);
            float s = 0.f;
            #pragma unroll 8
            for (int m = 0; m < 64; m++) s = fmaf(W[k * 64 + m], L[m * 64 + jj], s);
            val = s;
        } else {
            int kk = k - 128;
            if (j < 64)       val = Lz[(64 + kk) * 64 + j];
            else if (j < 128) val = Lr[(64 + kk) * 64 + (j - 64)];
            else              val = 0.f;
        }
        __nv_bfloat16 hb = __float2bfloat16(val);
        float hf = __bfloat162float(hb);
        __nv_bfloat16 lb = __float2bfloat16(val - hf);
        g_Bh16[j * 192 + k] = *reinterpret_cast<unsigned short*>(&hb);
        g_Bl16[j * 192 + k] = *reinterpret_cast<unsigned short*>(&lb);
    }
    if (i < 192) {
        int g = i >> 6, jj = i & 63;
        const float* b  = (g == 0) ? bz  : ((g == 1) ? br  : bh);
        const float* L  = (g == 0) ? Lz  : ((g == 1) ? Lr  : Lh);
        const float* bL = (g == 0) ? bLz : ((g == 1) ? bLr : bLh);
        float s = bL[jj];
        #pragma unroll 8
        for (int m = 0; m < 64; m++) s = fmaf(b[m], L[m * 64 + jj], s);
        g_c[i] = s;
    }
}

// ---------------- degree histogram + rank ----------------
__global__ void k_hist(const int* __restrict__ ei, const float* __restrict__ ew, int E) {
    int e = blockIdx.x * blockDim.x + threadIdx.x;
    if (e < E) {
        int c = ei[E + e];
        atomicAdd(&g_dinv[c], ew[e]);
        g_rank[e] = atomicAdd(&g_cnt[c], 1);
    }
}

// ---------------- dinv + exclusive scan ----------------
__global__ void k_scan1(int n, int E) {
    int tid = threadIdx.x;
    for (int i = tid; i < n; i += 1024) g_dinv[i] = rsqrtf(g_dinv[i]);

    __shared__ int s[1024];
    int per = (n + 1023) >> 10;
    int start = tid * per;
    int end = start + per; if (end > n) end = n; if (start > n) start = n;
    int sum = 0;
    for (int i = start; i < end; i++) sum += g_cnt[i];
    s[tid] = sum; __syncthreads();
    int v = sum;
    for (int d = 1; d < 1024; d <<= 1) {
        int t = (tid >= d) ? s[tid - d] : 0;
        __syncthreads();
        s[tid] += t;
        __syncthreads();
    }
    int pre = s[tid] - v;
    for (int i = start; i < end; i++) { g_offs[i] = pre; pre += g_cnt[i]; }
    if (tid == 0) g_offs[n] = E;
}

// ---------------- CSR fill (no atomic; rank precomputed) ----------------
__global__ void k_fill(const int* __restrict__ ei, const float* __restrict__ ew, int E) {
    int e = blockIdx.x * blockDim.x + threadIdx.x;
    if (e < E) {
        int r = ei[e];
        int c = ei[E + e];
        float nrm = g_dinv[r] * ew[e] * g_dinv[c];
        g_edge[g_offs[c] + g_rank[e]] = make_int2(r, __float_as_int(nrm));
    }
}

// ---------------- aggregation + h copy + bf16 split ----------------
__global__ __launch_bounds__(256) void k_agg(const float* __restrict__ x,
                                             const float* __restrict__ h, int n) {
    int warp = threadIdx.x >> 5, lane = threadIdx.x & 31;
    int node = blockIdx.x * 8 + warp;
    if (node >= n) return;
    const float4* xv = (const float4*)x;
    float di = g_dinv[node];
    float s = di * di;
    float4 a = xv[(size_t)node * 32 + lane];
    float4 acc = make_float4(s * a.x, s * a.y, s * a.z, s * a.w);
    int j = g_offs[node], j1 = g_offs[node + 1];
    for (; j + 3 < j1; j += 4) {
        int2 e0 = g_edge[j], e1 = g_edge[j + 1], e2 = g_edge[j + 2], e3 = g_edge[j + 3];
        float4 v0 = xv[(size_t)e0.x * 32 + lane];
        float4 v1 = xv[(size_t)e1.x * 32 + lane];
        float4 v2 = xv[(size_t)e2.x * 32 + lane];
        float4 v3 = xv[(size_t)e3.x * 32 + lane];
        float w0 = __int_as_float(e0.y), w1 = __int_as_float(e1.y);
        float w2 = __int_as_float(e2.y), w3 = __int_as_float(e3.y);
        acc.x = fmaf(w0, v0.x, acc.x); acc.y = fmaf(w0, v0.y, acc.y);
        acc.z = fmaf(w0, v0.z, acc.z); acc.w = fmaf(w0, v0.w, acc.w);
        acc.x = fmaf(w1, v1.x, acc.x); acc.y = fmaf(w1, v1.y, acc.y);
        acc.z = fmaf(w1, v1.z, acc.z); acc.w = fmaf(w1, v1.w, acc.w);
        acc.x = fmaf(w2, v2.x, acc.x); acc.y = fmaf(w2, v2.y, acc.y);
        acc.z = fmaf(w2, v2.z, acc.z); acc.w = fmaf(w2, v2.w, acc.w);
        acc.x = fmaf(w3, v3.x, acc.x); acc.y = fmaf(w3, v3.y, acc.y);
        acc.z = fmaf(w3, v3.z, acc.z); acc.w = fmaf(w3, v3.w, acc.w);
    }
    for (; j < j1; j++) {
        int2 e0 = g_edge[j];
        float4 v0 = xv[(size_t)e0.x * 32 + lane];
        float w0 = __int_as_float(e0.y);
        acc.x = fmaf(w0, v0.x, acc.x); acc.y = fmaf(w0, v0.y, acc.y);
        acc.z = fmaf(w0, v0.z, acc.z); acc.w = fmaf(w0, v0.w, acc.w);
    }
    uint32_t h0, l0, h1, l1;
    split2(acc.x, acc.y, h0, l0);
    split2(acc.z, acc.w, h1, l1);
    *(uint2*)&g_Ahp[(size_t)node * 96 + lane * 2] = make_uint2(h0, h1);
    *(uint2*)&g_Alp[(size_t)node * 96 + lane * 2] = make_uint2(l0, l1);
    if (lane < 16) {
        float4 hv = ((const float4*)h)[(size_t)node * 16 + lane];
        split2(hv.x, hv.y, h0, l0);
        split2(hv.z, hv.w, h1, l1);
        *(uint2*)&g_Ahp[(size_t)node * 96 + 64 + lane * 2] = make_uint2(h0, h1);
        *(uint2*)&g_Alp[(size_t)node * 96 + 64 + lane * 2] = make_uint2(l0, l1);
    }
}

// ---------------- fused 3xBF16 GEMM + finalize ----------------
// CTA 64(M) x 192(N). K=192 in 6 chunks of 32 (16 u32 kp), double-buffered.
// 8 warps = 2(M) x 4(N); warp tile 32x48 = 2 mf x 6 nt (m16n8k16).
// Fragments via ldmatrix.x4. 2 CTAs/SM (80KB smem).
#define PADK 20
#define F_A   0
#define F_AL  1280
#define F_BH  2560
#define F_BL  6400
#define F_BUF 10240
#define PP 200
#define SMEM_GEMM_BYTES (2 * F_BUF * 4)

__global__ __launch_bounds__(256) void k_gemm_fused(
        const float* __restrict__ h, const float* __restrict__ Lh,
        const float* __restrict__ Wo, const float* __restrict__ bo,
        float* __restrict__ out, int n) {
    extern __shared__ float smf[];
    uint32_t sb = smem_u32(smf);
    int tid = threadIdx.x;
    int wid = tid >> 5, lane = tid & 31;
    int warpM = wid >> 2, warpN = wid & 3;
    int gid = lane >> 2, tig = lane & 3;
    int msel = lane >> 3, rr = lane & 7;
    int rowBase = blockIdx.x * 64;

    float d[2][6][4];
    #pragma unroll
    for (int mf = 0; mf < 2; mf++)
        #pragma unroll
        for (int nt = 0; nt < 6; nt++)
            #pragma unroll
            for (int q = 0; q < 4; q++) d[mf][nt][q] = 0.f;

    // lane-invariant fragment byte offsets within a buffer
    // A: row = warpM*32 + mf*16 + (msel&1)*8 + rr ; kp = ks*8 + (msel>>1)*4
    uint32_t aoff = ((warpM * 32 + (msel & 1) * 8 + rr) * PADK + (msel >> 1) * 4) * 4;
    // B: n = warpN*48 + ntp*16 + (msel>>1)*8 + rr ; kp = ks*8 + (msel&1)*4
    uint32_t boff = ((warpN * 48 + (msel >> 1) * 8 + rr) * PADK + (msel & 1) * 4) * 4;

    // --- stage chunk 0 ---
    {
        uint32_t base = sb;
        const uint32_t* Ah = g_Ahp + (size_t)rowBase * 96;
        const uint32_t* Al = g_Alp + (size_t)rowBase * 96;
        int row = tid >> 2, q = tid & 3;               // 64 rows x 4 quads
        cpa16(base + (F_A  + row * PADK + q * 4) * 4, Ah + (size_t)row * 96 + q * 4);
        cpa16(base + (F_AL + row * PADK + q * 4) * 4, Al + (size_t)row * 96 + q * 4);
        #pragma unroll
        for (int t = 0; t < 3; t++) {                  // 192 rows x 4 quads
            int idx = tid + t * 256;
            int jrow = idx >> 2, jq = idx & 3;
            cpa16(base + (F_BH + jrow * PADK + jq * 4) * 4, g_Bh16 + jrow * 192 + jq * 8);
            cpa16(base + (F_BL + jrow * PADK + jq * 4) * 4, g_Bl16 + jrow * 192 + jq * 8);
        }
        asm volatile("cp.async.commit_group;");
    }

    for (int c = 0; c < 6; c++) {
        if (c + 1 < 6) {
            uint32_t base = sb + ((c + 1) & 1) * (F_BUF * 4);
            int cc = c + 1;
            const uint32_t* Ah = g_Ahp + (size_t)rowBase * 96 + cc * 16;
            const uint32_t* Al = g_Alp + (size_t)rowBase * 96 + cc * 16;
            int row = tid >> 2, q = tid & 3;
            cpa16(base + (F_A  + row * PADK + q * 4) * 4, Ah + (size_t)row * 96 + q * 4);
            cpa16(base + (F_AL + row * PADK + q * 4) * 4, Al + (size_t)row * 96 + q * 4);
            const unsigned short* Bh = g_Bh16 + cc * 32;
            const unsigned short* Bl = g_Bl16 + cc * 32;
            #pragma unroll
            for (int t = 0; t < 3; t++) {
                int idx = tid + t * 256;
                int jrow = idx >> 2, jq = idx & 3;
                cpa16(base + (F_BH + jrow * PADK + jq * 4) * 4, Bh + jrow * 192 + jq * 8);
                cpa16(base + (F_BL + jrow * PADK + jq * 4) * 4, Bl + jrow * 192 + jq * 8);
            }
            asm volatile("cp.async.commit_group;");
            asm volatile("cp.async.wait_group 1;");
        } else {
            asm volatile("cp.async.wait_group 0;");
        }
        __syncthreads();

        uint32_t bufb = sb + (c & 1) * (F_BUF * 4);
        uint32_t ah_base = bufb + F_A * 4  + aoff;
        uint32_t al_base = bufb + F_AL * 4 + aoff;
        uint32_t bh_base = bufb + F_BH * 4 + boff;
        uint32_t bl_base = bufb + F_BL * 4 + boff;

        #pragma unroll
        for (int ks = 0; ks < 2; ks++) {
            uint32_t kso = ks * 8 * 4;                  // kp step in bytes
            uint32_t ahi[2][4], alo[2][4];
            #pragma unroll
            for (int mf = 0; mf < 2; mf++) {
                uint32_t ao = mf * 16 * PADK * 4 + kso;
                ldsm4(ahi[mf][0], ahi[mf][1], ahi[mf][2], ahi[mf][3], ah_base + ao);
                ldsm4(alo[mf][0], alo[mf][1], alo[mf][2], alo[mf][3], al_base + ao);
            }
            #pragma unroll
            for (int ntp = 0; ntp < 3; ntp++) {
                uint32_t bo_ = ntp * 16 * PADK * 4 + kso;
                uint32_t bh0, bh1, bh2, bh3, bl0, bl1, bl2, bl3;
                ldsm4(bh0, bh1, bh2, bh3, bh_base + bo_);
                ldsm4(bl0, bl1, bl2, bl3, bl_base + bo_);
                #pragma unroll
                for (int mf = 0; mf < 2; mf++) {
                    mma_bf16(d[mf][ntp * 2],     ahi[mf], bh0, bh1);
                    mma_bf16(d[mf][ntp * 2],     ahi[mf], bl0, bl1);
                    mma_bf16(d[mf][ntp * 2],     alo[mf], bh0, bh1);
                    mma_bf16(d[mf][ntp * 2 + 1], ahi[mf], bh2, bh3);
                    mma_bf16(d[mf][ntp * 2 + 1], ahi[mf], bl2, bl3);
                    mma_bf16(d[mf][ntp * 2 + 1], alo[mf], bh2, bh3);
                }
            }
        }
        __syncthreads();
    }

    // ---- epilogue: accumulators -> Pbuf (reuse staging smem) ----
    float* Pbuf = smf;                         // 64 x PP = 12800 floats
    float* Lhb  = smf + 12800;                 // 64 x 65 = 4160
    float* sWo  = smf + 16960;                 // 64
    float* sc   = smf + 17024;                 // 192
    #pragma unroll
    for (int mf = 0; mf < 2; mf++) {
        int rl = warpM * 32 + mf * 16 + gid;
        #pragma unroll
        for (int nt = 0; nt < 6; nt++) {
            int col = warpN * 48 + nt * 8 + tig * 2;
            *(float2*)(Pbuf + rl * PP + col)       = make_float2(d[mf][nt][0], d[mf][nt][1]);
            *(float2*)(Pbuf + (rl + 8) * PP + col) = make_float2(d[mf][nt][2], d[mf][nt][3]);
        }
    }
    for (int i = tid; i < 4096; i += 256) {
        int k = i >> 6, j = i & 63;
        Lhb[k * 65 + j] = Lh[(64 + k) * 64 + j];
    }
    if (tid < 64) sWo[tid] = Wo[tid];
    if (tid < 192) sc[tid] = g_c[tid];
    __syncthreads();

    // ---- finalize: each warp handles 8 nodes ----
    float bo0 = bo[0];
    #pragma unroll 1
    for (int i = 0; i < 8; i++) {
        int nl = wid * 8 + i;
        int node = rowBase + nl;
        if (node >= n) break;
        const float* p = Pbuf + nl * PP;
        float z0 = sigf(p[lane]       + sc[lane]);
        float z1 = sigf(p[lane + 32]  + sc[lane + 32]);
        float r0 = sigf(p[lane + 64]  + sc[lane + 64]);
        float r1 = sigf(p[lane + 96]  + sc[lane + 96]);
        float q0 =      p[lane + 128] + sc[lane + 128];
        float q1 =      p[lane + 160] + sc[lane + 160];

        float h0 = h[(size_t)node * 64 + lane];
        float h1 = h[(size_t)node * 64 + lane + 32];
        float v0 = h0 * r0, v1 = h1 * r1;

        float acc0 = q0, acc1 = q1;
        #pragma unroll
        for (int k = 0; k < 32; k++) {
            float vk = __shfl_sync(0xffffffffu, v0, k);
            acc0 = fmaf(vk, Lhb[k * 65 + lane], acc0);
            acc1 = fmaf(vk, Lhb[k * 65 + lane + 32], acc1);
        }
        #pragma unroll
        for (int k = 0; k < 32; k++) {
            float vk = __shfl_sync(0xffffffffu, v1, k);
            acc0 = fmaf(vk, Lhb[(k + 32) * 65 + lane], acc0);
            acc1 = fmaf(vk, Lhb[(k + 32) * 65 + lane + 32], acc1);
        }
        float t0 = tanhf(acc0), t1 = tanhf(acc1);
        float hn0 = z0 * h0 + (1.f - z0) * t0;
        float hn1 = z1 * h1 + (1.f - z1) * t1;

        out[n + (size_t)node * 64 + lane]      = hn0;
        out[n + (size_t)node * 64 + lane + 32] = hn1;

        float dot = hn0 * sWo[lane] + hn1 * sWo[lane + 32];
        #pragma unroll
        for (int o = 16; o; o >>= 1) dot += __shfl_down_sync(0xffffffffu, dot, o);
        if (lane == 0) out[node] = dot + bo0;
    }
}

// ---------------- launcher ----------------
extern "C" void kernel_launch(void* const* d_in, const int* in_sizes, int n_in,
                              void* d_out, int out_size) {
    const float* x   = (const float*)d_in[0];
    const int*   ei  = (const int*)  d_in[1];
    const float* ew  = (const float*)d_in[2];
    const float* h   = (const float*)d_in[3];
    const float* Wz  = (const float*)d_in[4];
    const float* bz  = (const float*)d_in[5];
    const float* Wr  = (const float*)d_in[6];
    const float* br  = (const float*)d_in[7];
    const float* Wh  = (const float*)d_in[8];
    const float* bh  = (const float*)d_in[9];
    const float* Lz  = (const float*)d_in[10];
    const float* bLz = (const float*)d_in[11];
    const float* Lr  = (const float*)d_in[12];
    const float* bLr = (const float*)d_in[13];
    const float* Lh  = (const float*)d_in[14];
    const float* bLh = (const float*)d_in[15];
    const float* Wo  = (const float*)d_in[16];
    const float* bo  = (const float*)d_in[17];
    float* out = (float*)d_out;

    int N = in_sizes[0] / 128;
    int E = in_sizes[2];
    int setup_elems = (N > 192 * 192) ? N : 192 * 192;

    cudaFuncSetAttribute(k_gemm_fused, cudaFuncAttributeMaxDynamicSharedMemorySize,
                         SMEM_GEMM_BYTES);

    k_setup<<<(setup_elems + 255) / 256, 256>>>(Wz, Wr, Wh, Lz, Lr, Lh,
                                                bz, br, bh, bLz, bLr, bLh, N);
    k_hist<<<(E + 255) / 256, 256>>>(ei, ew, E);
    k_scan1<<<1, 1024>>>(N, E);
    k_fill<<<(E + 255) / 256, 256>>>(ei, ew, E);
    k_agg<<<(N + 7) / 8, 256>>>(x, h, N);
    k_gemm_fused<<<(N + 63) / 64, 256, SMEM_GEMM_BYTES>>>(h, Lh, Wo, bo, out, N);
}